// round 3
// baseline (speedup 1.0000x reference)
#include <cuda_runtime.h>
#include <cuda_bf16.h>
#include <cstddef>
#include <cstdint>

// Problem constants
// B=16, H=W=48 -> nq=2304, D=512, NH=8, DK=DV=64, RATIO=3 -> conv 4x4 stride 3 pad 1 -> 16x16 -> nk=256
#define BB   16
#define NQ   2304
#define NK   256
#define DD   512
#define NHH  8
#define DK_  64
#define NBH  (BB*NHH)          // 128

// -------- device scratch (allowed: __device__ globals, no cudaMalloc) --------
// g_Q doubles as the attention-output buffer: scores_kernel is the last reader
// of Q, and attv_kernel (which writes O) only runs after headmix_kernel, so
// the reuse is safe under stream ordering.
__device__ float g_Q  [(size_t)BB*NQ*DD];        // 75.5 MB  Q projection, then att output
__device__ float g_X  [(size_t)BB*NK*DD];        // 8.4 MB   conv+LN result
__device__ float g_K  [(size_t)BB*NK*DD];        // 8.4 MB
__device__ float g_V  [(size_t)BB*NK*DD];        // 8.4 MB
__device__ float g_att[(size_t)NBH*NQ*NK];       // 302 MB   scores, then centered softmax (in-place)
__device__ float g_ssq[NBH];
__device__ float g_rstd[NBH];

// ---------------- reductions ----------------
__device__ __forceinline__ float blockSum(float v, float* sm, int warps) {
    int lane = threadIdx.x & 31, w = threadIdx.x >> 5;
#pragma unroll
    for (int o = 16; o > 0; o >>= 1) v += __shfl_xor_sync(0xffffffffu, v, o);
    if (lane == 0) sm[w] = v;
    __syncthreads();
    float r = (lane < warps) ? sm[lane] : 0.f;
#pragma unroll
    for (int o = 16; o > 0; o >>= 1) r += __shfl_xor_sync(0xffffffffu, r, o);
    return r; // broadcast to all threads
}

__device__ __forceinline__ float blockMax(float v, float* sm, int warps) {
    int lane = threadIdx.x & 31, w = threadIdx.x >> 5;
#pragma unroll
    for (int o = 16; o > 0; o >>= 1) v = fmaxf(v, __shfl_xor_sync(0xffffffffu, v, o));
    if (lane == 0) sm[w] = v;
    __syncthreads();
    float r = (lane < warps) ? sm[lane] : -3.4e38f;
#pragma unroll
    for (int o = 16; o > 0; o >>= 1) r = fmaxf(r, __shfl_xor_sync(0xffffffffu, r, o));
    return r;
}

// ---------------- generic SGEMM: C = A(MxK) @ B(KxN) + bias ----------------
// 128x128 tile, BK=8, 256 threads, 8x8 per thread. M%128==0, N%128==0, K%8==0.
__global__ __launch_bounds__(256, 2) void sgemm_kernel(
    const float* __restrict__ A, const float* __restrict__ B,
    const float* __restrict__ bias, float* __restrict__ C,
    int M, int N, int K)
{
    __shared__ float As[8][128];
    __shared__ float Bs[8][128];
    const int tid = threadIdx.x;
    const int tx = tid & 15;          // col group
    const int ty = tid >> 4;          // row group
    const int rowA = blockIdx.y * 128;
    const int colB = blockIdx.x * 128;
    const int aRow = tid >> 1;
    const int aCol = (tid & 1) * 4;
    const int bRow = tid >> 5;
    const int bCol = (tid & 31) * 4;

    const float* Aptr = A + (size_t)(rowA + aRow) * K + aCol;
    const float* Bptr = B + (size_t)bRow * N + colB + bCol;

    float acc[8][8] = {};
    for (int k0 = 0; k0 < K; k0 += 8) {
        float4 av = *reinterpret_cast<const float4*>(Aptr + k0);
        float4 bv = *reinterpret_cast<const float4*>(Bptr + (size_t)k0 * N);
        As[aCol + 0][aRow] = av.x; As[aCol + 1][aRow] = av.y;
        As[aCol + 2][aRow] = av.z; As[aCol + 3][aRow] = av.w;
        *reinterpret_cast<float4*>(&Bs[bRow][bCol]) = bv;
        __syncthreads();
#pragma unroll
        for (int kk = 0; kk < 8; kk++) {
            float a[8], b[8];
#pragma unroll
            for (int i = 0; i < 8; i++) a[i] = As[kk][ty * 8 + i];
#pragma unroll
            for (int j = 0; j < 8; j++) b[j] = Bs[kk][tx * 8 + j];
#pragma unroll
            for (int i = 0; i < 8; i++)
#pragma unroll
                for (int j = 0; j < 8; j++) acc[i][j] = fmaf(a[i], b[j], acc[i][j]);
        }
        __syncthreads();
    }
#pragma unroll
    for (int i = 0; i < 8; i++) {
        int r = rowA + ty * 8 + i;
#pragma unroll
        for (int j = 0; j < 8; j += 4) {
            int c = colB + tx * 8 + j;
            float4 v;
            v.x = acc[i][j + 0] + (bias ? bias[c + 0] : 0.f);
            v.y = acc[i][j + 1] + (bias ? bias[c + 1] : 0.f);
            v.z = acc[i][j + 2] + (bias ? bias[c + 2] : 0.f);
            v.w = acc[i][j + 3] + (bias ? bias[c + 3] : 0.f);
            *reinterpret_cast<float4*>(&C[(size_t)r * N + c]) = v;
        }
    }
}

// ---------------- fused depthwise conv (4x4, stride 3, pad 1) + LayerNorm ----------------
// grid (256 out-positions, 16 batch), 512 threads (one per channel)
__global__ __launch_bounds__(512) void conv_ln_kernel(
    const float* __restrict__ q, const float* __restrict__ srw,
    const float* __restrict__ srb, const float* __restrict__ lng,
    const float* __restrict__ lnb)
{
    __shared__ float sm[16];
    const int b = blockIdx.y;
    const int pos = blockIdx.x;            // 0..255
    const int c = threadIdx.x;             // 0..511
    const int oh = pos >> 4, ow = pos & 15;

    float acc = srb[c];
    const float* w = srw + c * 16;         // (D,1,4,4)
#pragma unroll
    for (int kh = 0; kh < 4; kh++) {
        int h = oh * 3 - 1 + kh;
        if ((unsigned)h >= 48u) continue;
#pragma unroll
        for (int kw = 0; kw < 4; kw++) {
            int wv = ow * 3 - 1 + kw;
            if ((unsigned)wv >= 48u) continue;
            acc = fmaf(q[((size_t)b * NQ + h * 48 + wv) * DD + c], w[kh * 4 + kw], acc);
        }
    }
    // LayerNorm over 512 channels (two-pass, matches jnp.var)
    float s = blockSum(acc, sm, 16);
    float mean = s * (1.f / 512.f);
    __syncthreads();
    float d = acc - mean;
    float vs = blockSum(d * d, sm, 16);
    float var = vs * (1.f / 512.f);
    float y = d * rsqrtf(var + 1e-5f) * lng[c] + lnb[c];
    g_X[((size_t)b * NK + pos) * DD + c] = y;
}

// ---------------- batched scores: att[bh,q,k] = (Q[b,q,h,:]·K[b,k,h,:]) / 8 ----------------
// grid (nk/64, nq/64, 128 bh), 256 threads, 4x4 per thread, K-dim=64 in 16-chunks
__global__ __launch_bounds__(256, 2) void scores_kernel()
{
    __shared__ float Ast[16][64];
    __shared__ float Bst[16][64];
    const int bh = blockIdx.z;
    const int b = bh >> 3, h = bh & 7;
    const int q0 = blockIdx.y * 64;
    const int k0 = blockIdx.x * 64;
    const int tid = threadIdx.x;
    const int tx = tid & 15, ty = tid >> 4;
    const int lr = tid >> 2;              // 0..63
    const int ld = (tid & 3) * 4;         // 0,4,8,12

    const float* Aptr = g_Q + ((size_t)b * NQ + q0 + lr) * DD + h * DK_ + ld;
    const float* Bptr = g_K + ((size_t)b * NK + k0 + lr) * DD + h * DK_ + ld;

    float acc[4][4] = {};
#pragma unroll
    for (int d0 = 0; d0 < 64; d0 += 16) {
        float4 av = *reinterpret_cast<const float4*>(Aptr + d0);
        float4 bv = *reinterpret_cast<const float4*>(Bptr + d0);
        Ast[ld + 0][lr] = av.x; Ast[ld + 1][lr] = av.y; Ast[ld + 2][lr] = av.z; Ast[ld + 3][lr] = av.w;
        Bst[ld + 0][lr] = bv.x; Bst[ld + 1][lr] = bv.y; Bst[ld + 2][lr] = bv.z; Bst[ld + 3][lr] = bv.w;
        __syncthreads();
#pragma unroll
        for (int dd = 0; dd < 16; dd++) {
            float a[4], bb[4];
#pragma unroll
            for (int i = 0; i < 4; i++) a[i] = Ast[dd][ty * 4 + i];
#pragma unroll
            for (int j = 0; j < 4; j++) bb[j] = Bst[dd][tx * 4 + j];
#pragma unroll
            for (int i = 0; i < 4; i++)
#pragma unroll
                for (int j = 0; j < 4; j++) acc[i][j] = fmaf(a[i], bb[j], acc[i][j]);
        }
        __syncthreads();
    }
    const float scale = 0.125f; // 1/sqrt(64)
#pragma unroll
    for (int i = 0; i < 4; i++) {
        int qq = q0 + ty * 4 + i;
        float4 v = { acc[i][0] * scale, acc[i][1] * scale, acc[i][2] * scale, acc[i][3] * scale };
        *reinterpret_cast<float4*>(&g_att[((size_t)bh * NQ + qq) * NK + k0 + tx * 4]) = v;
    }
}

__global__ void zero_stats_kernel() {
    if (threadIdx.x < NBH) g_ssq[threadIdx.x] = 0.f;
}

// ---------------- head-mix (1x1 conv over heads) + softmax + centered ssq ----------------
// grid (B*NQ) blocks, 256 threads (one per k). Writes p - 1/256 IN-PLACE into g_att.
// Safe: each block exclusively owns slice [b, :, q, :]; all reads complete before writes.
__global__ __launch_bounds__(256) void headmix_kernel(
    const float* __restrict__ tw, const float* __restrict__ tb)
{
    __shared__ float raw[8][256];
    __shared__ float sm[8];
    const int bq = blockIdx.x;
    const int b = bq / NQ, q = bq % NQ;
    const int k = threadIdx.x;

    const size_t base = ((size_t)b * NHH * NQ + q) * NK + k;   // head i: + i*NQ*NK
#pragma unroll
    for (int i = 0; i < 8; i++) raw[i][k] = g_att[base + (size_t)i * NQ * NK];
    __syncthreads();

    float mixed[8];
#pragma unroll
    for (int o = 0; o < 8; o++) {
        float v = tb[o];
#pragma unroll
        for (int i = 0; i < 8; i++) v = fmaf(tw[o * 8 + i], raw[i][k], v);
        mixed[o] = v;
    }

#pragma unroll
    for (int o = 0; o < 8; o++) {
        __syncthreads();                      // sm free for reuse
        float mx = blockMax(mixed[o], sm, 8);
        __syncthreads();
        float e = __expf(mixed[o] - mx);
        float s = blockSum(e, sm, 8);
        float p = e / s;
        float c = p - 0.00390625f;            // p - 1/256 (analytic InstanceNorm mean)
        g_att[base + (size_t)o * NQ * NK] = c;
        __syncthreads();
        float sq = blockSum(c * c, sm, 8);
        if (k == 0) atomicAdd(&g_ssq[b * 8 + o], sq);
    }
}

__global__ void rstd_kernel() {
    int i = threadIdx.x;
    if (i < NBH) g_rstd[i] = rsqrtf(g_ssq[i] * (1.f / ((float)NQ * (float)NK)) + 1e-5f);
}

// ---------------- att @ V with InstanceNorm folded: O = rstd * (att_centered @ V) ----------------
// grid (nq/128, 128 bh), 256 threads, tile 128q x 64d, k-chunks of 16, 8x4 per thread
// Writes into g_Q (reused as O buffer; Q itself is dead after scores_kernel).
__global__ __launch_bounds__(256, 2) void attv_kernel()
{
    __shared__ float Ast[16][128];
    __shared__ float Bs[16][64];
    const int bh = blockIdx.y;
    const int b = bh >> 3, h = bh & 7;
    const int q0 = blockIdx.x * 128;
    const int tid = threadIdx.x;
    const int tx = tid & 15, ty = tid >> 4;
    const int q_l = tid >> 1, kq = (tid & 1) * 8;     // A loads: 8 k per thread
    const int k_l = tid >> 4, d4 = (tid & 15) * 4;    // B loads: 4 d per thread

    const float* Abase = g_att + ((size_t)bh * NQ + q0 + q_l) * NK + kq;
    const float* Bbase = g_V + ((size_t)b * NK + k_l) * DD + h * DK_ + d4;

    float acc[8][4] = {};
    for (int c0 = 0; c0 < NK; c0 += 16) {
        float4 a0 = *reinterpret_cast<const float4*>(Abase + c0);
        float4 a1 = *reinterpret_cast<const float4*>(Abase + c0 + 4);
        float4 bv = *reinterpret_cast<const float4*>(Bbase + (size_t)c0 * DD);
        Ast[kq + 0][q_l] = a0.x; Ast[kq + 1][q_l] = a0.y; Ast[kq + 2][q_l] = a0.z; Ast[kq + 3][q_l] = a0.w;
        Ast[kq + 4][q_l] = a1.x; Ast[kq + 5][q_l] = a1.y; Ast[kq + 6][q_l] = a1.z; Ast[kq + 7][q_l] = a1.w;
        *reinterpret_cast<float4*>(&Bs[k_l][d4]) = bv;
        __syncthreads();
#pragma unroll
        for (int kk = 0; kk < 16; kk++) {
            float a[8], bb[4];
#pragma unroll
            for (int i = 0; i < 8; i++) a[i] = Ast[kk][ty * 8 + i];
#pragma unroll
            for (int j = 0; j < 4; j++) bb[j] = Bs[kk][tx * 4 + j];
#pragma unroll
            for (int i = 0; i < 8; i++)
#pragma unroll
                for (int j = 0; j < 4; j++) acc[i][j] = fmaf(a[i], bb[j], acc[i][j]);
        }
        __syncthreads();
    }
    const float rs = g_rstd[bh];
#pragma unroll
    for (int i = 0; i < 8; i++) {
        int qq = q0 + ty * 8 + i;
        float4 v = { acc[i][0] * rs, acc[i][1] * rs, acc[i][2] * rs, acc[i][3] * rs };
        *reinterpret_cast<float4*>(&g_Q[((size_t)b * NQ + qq) * DD + h * DK_ + tx * 4]) = v;
    }
}

// ---------------- launch ----------------
extern "C" void kernel_launch(void* const* d_in, const int* in_sizes, int n_in,
                              void* d_out, int out_size)
{
    const float* queries = (const float*)d_in[0];
    const float* Wq = (const float*)d_in[1];
    const float* bq = (const float*)d_in[2];
    const float* Wk = (const float*)d_in[3];
    const float* bk = (const float*)d_in[4];
    const float* Wv = (const float*)d_in[5];
    const float* bv = (const float*)d_in[6];
    const float* Wo = (const float*)d_in[7];
    const float* bo = (const float*)d_in[8];
    const float* srw = (const float*)d_in[9];
    const float* srb = (const float*)d_in[10];
    const float* lng = (const float*)d_in[11];
    const float* lnb = (const float*)d_in[12];
    const float* tw = (const float*)d_in[13];
    const float* tb = (const float*)d_in[14];
    float* out = (float*)d_out;

    float *pQ, *pX;
    cudaGetSymbolAddress((void**)&pQ, g_Q);
    cudaGetSymbolAddress((void**)&pX, g_X);
    float *pK, *pV;
    cudaGetSymbolAddress((void**)&pK, g_K);
    cudaGetSymbolAddress((void**)&pV, g_V);

    // 1. Q projection: (B*NQ, D) @ (D, D) + bq
    sgemm_kernel<<<dim3(DD / 128, (BB * NQ) / 128), 256>>>(queries, Wq, bq, pQ, BB * NQ, DD, DD);

    // 2. spatial reduction conv + LayerNorm
    conv_ln_kernel<<<dim3(NK, BB), 512>>>(queries, srw, srb, lng, lnb);

    // 3/4. K, V projections: (B*NK, D) @ (D, D)
    sgemm_kernel<<<dim3(DD / 128, (BB * NK) / 128), 256>>>(pX, Wk, bk, pK, BB * NK, DD, DD);
    sgemm_kernel<<<dim3(DD / 128, (BB * NK) / 128), 256>>>(pX, Wv, bv, pV, BB * NK, DD, DD);

    // 5. attention scores (batched over 128 b*h)
    scores_kernel<<<dim3(NK / 64, NQ / 64, NBH), 256>>>();

    // 6. zero InstanceNorm accumulators
    zero_stats_kernel<<<1, 128>>>();

    // 7. head mix + softmax + centered sum-of-squares (in-place on g_att)
    headmix_kernel<<<BB * NQ, 256>>>(tw, tb);

    // 8. finalize rstd
    rstd_kernel<<<1, 128>>>();

    // 9. (att - mean)/std @ V  (batched) -> writes O into g_Q
    attv_kernel<<<dim3(NQ / 128, NBH), 256>>>();

    // 10. output projection: (B*NQ, D) @ (D, D) + bo
    sgemm_kernel<<<dim3(DD / 128, (BB * NQ) / 128), 256>>>(pQ, Wo, bo, out, BB * NQ, DD, DD);
}

// round 4
// speedup vs baseline: 1.2055x; 1.2055x over previous
#include <cuda_runtime.h>
#include <cuda_bf16.h>
#include <cstddef>
#include <cstdint>

// Problem constants
#define BB   16
#define NQ   2304
#define NK   256
#define DD   512
#define NHH  8
#define DK_  64
#define NBH  (BB*NHH)          // 128

// -------- device scratch --------
__device__ float g_Q  [(size_t)BB*NQ*DD];        // Q projection, later att output
__device__ float g_X  [(size_t)BB*NK*DD];
__device__ float g_K  [(size_t)BB*NK*DD];
__device__ float g_V  [(size_t)BB*NK*DD];
__device__ float g_att[(size_t)NBH*NQ*NK];       // scores -> centered softmax (in-place)
__device__ float g_ssq[NBH];
__device__ float g_rstd[NBH];

// ---------------- reductions ----------------
__device__ __forceinline__ float blockSum(float v, float* sm, int warps) {
    int lane = threadIdx.x & 31, w = threadIdx.x >> 5;
#pragma unroll
    for (int o = 16; o > 0; o >>= 1) v += __shfl_xor_sync(0xffffffffu, v, o);
    if (lane == 0) sm[w] = v;
    __syncthreads();
    float r = (lane < warps) ? sm[lane] : 0.f;
#pragma unroll
    for (int o = 16; o > 0; o >>= 1) r += __shfl_xor_sync(0xffffffffu, r, o);
    return r;
}

// ---------------- SGEMM v2: double-buffered, conflict-free warp layout ----------------
// C = A(MxK) @ B(KxN) + bias. 128x128 tile, BK=8, 256 thr.
// Warp grid 4(M)x2(N), warp tile 32x64. Thread: rows {r0..r0+3, r0+16..19}, cols {c0..c0+3, c0+32..35}.
__global__ __launch_bounds__(256, 2) void sgemm2_kernel(
    const float* __restrict__ A, const float* __restrict__ B,
    const float* __restrict__ bias, float* __restrict__ C,
    int M, int N, int K)
{
    __shared__ float As[2][8][128];
    __shared__ float Bs[2][8][128];
    const int tid = threadIdx.x;
    const int lane = tid & 31;
    const int warp = tid >> 5;
    const int warpM = warp >> 1;          // 0..3
    const int warpN = warp & 1;           // 0..1
    const int tm = lane >> 3;             // 0..3
    const int tn = lane & 7;              // 0..7
    const int r0 = warpM * 32 + tm * 4;   // +16 second group
    const int c0 = warpN * 64 + tn * 4;   // +32 second group

    const int rowA = blockIdx.y * 128;
    const int colB = blockIdx.x * 128;
    const int aRow = tid >> 1;
    const int aCol = (tid & 1) * 4;
    const int bRow = tid >> 5;            // 0..7
    const int bCol = (tid & 31) * 4;

    const float* Aptr = A + (size_t)(rowA + aRow) * K + aCol;
    const float* Bptr = B + (size_t)bRow * N + colB + bCol;

    // preload tile 0
    float4 apf = *reinterpret_cast<const float4*>(Aptr);
    float4 bpf = *reinterpret_cast<const float4*>(Bptr);
    As[0][aCol + 0][aRow] = apf.x; As[0][aCol + 1][aRow] = apf.y;
    As[0][aCol + 2][aRow] = apf.z; As[0][aCol + 3][aRow] = apf.w;
    *reinterpret_cast<float4*>(&Bs[0][bRow][bCol]) = bpf;
    __syncthreads();

    float acc[8][8] = {};
    int buf = 0;
    for (int k0 = 0; k0 < K; k0 += 8) {
        const bool hasNext = (k0 + 8) < K;
        if (hasNext) {
            apf = *reinterpret_cast<const float4*>(Aptr + k0 + 8);
            bpf = *reinterpret_cast<const float4*>(Bptr + (size_t)(k0 + 8) * N);
        }
#pragma unroll
        for (int kk = 0; kk < 8; kk++) {
            float4 a0 = *reinterpret_cast<const float4*>(&As[buf][kk][r0]);
            float4 a1 = *reinterpret_cast<const float4*>(&As[buf][kk][r0 + 16]);
            float4 b0 = *reinterpret_cast<const float4*>(&Bs[buf][kk][c0]);
            float4 b1 = *reinterpret_cast<const float4*>(&Bs[buf][kk][c0 + 32]);
            float av[8] = { a0.x, a0.y, a0.z, a0.w, a1.x, a1.y, a1.z, a1.w };
            float bv[8] = { b0.x, b0.y, b0.z, b0.w, b1.x, b1.y, b1.z, b1.w };
#pragma unroll
            for (int i = 0; i < 8; i++)
#pragma unroll
                for (int j = 0; j < 8; j++) acc[i][j] = fmaf(av[i], bv[j], acc[i][j]);
        }
        if (hasNext) {
            int nb = buf ^ 1;
            As[nb][aCol + 0][aRow] = apf.x; As[nb][aCol + 1][aRow] = apf.y;
            As[nb][aCol + 2][aRow] = apf.z; As[nb][aCol + 3][aRow] = apf.w;
            *reinterpret_cast<float4*>(&Bs[nb][bRow][bCol]) = bpf;
            __syncthreads();
            buf = nb;
        }
    }
#pragma unroll
    for (int i = 0; i < 8; i++) {
        int r = rowA + ((i < 4) ? (r0 + i) : (r0 + 16 + i - 4));
#pragma unroll
        for (int jg = 0; jg < 2; jg++) {
            int c = colB + c0 + jg * 32;
            float4 v;
            v.x = acc[i][jg * 4 + 0] + bias[c + 0];
            v.y = acc[i][jg * 4 + 1] + bias[c + 1];
            v.z = acc[i][jg * 4 + 2] + bias[c + 2];
            v.w = acc[i][jg * 4 + 3] + bias[c + 3];
            *reinterpret_cast<float4*>(&C[(size_t)r * N + c]) = v;
        }
    }
}

// ---------------- fused depthwise conv (4x4, stride 3, pad 1) + LayerNorm ----------------
__global__ __launch_bounds__(512) void conv_ln_kernel(
    const float* __restrict__ q, const float* __restrict__ srw,
    const float* __restrict__ srb, const float* __restrict__ lng,
    const float* __restrict__ lnb)
{
    __shared__ float sm[16];
    const int b = blockIdx.y;
    const int pos = blockIdx.x;
    const int c = threadIdx.x;
    const int oh = pos >> 4, ow = pos & 15;

    float acc = srb[c];
    const float* w = srw + c * 16;
#pragma unroll
    for (int kh = 0; kh < 4; kh++) {
        int h = oh * 3 - 1 + kh;
        if ((unsigned)h >= 48u) continue;
#pragma unroll
        for (int kw = 0; kw < 4; kw++) {
            int wv = ow * 3 - 1 + kw;
            if ((unsigned)wv >= 48u) continue;
            acc = fmaf(q[((size_t)b * NQ + h * 48 + wv) * DD + c], w[kh * 4 + kw], acc);
        }
    }
    float s = blockSum(acc, sm, 16);
    float mean = s * (1.f / 512.f);
    __syncthreads();
    float d = acc - mean;
    float vs = blockSum(d * d, sm, 16);
    float var = vs * (1.f / 512.f);
    float y = d * rsqrtf(var + 1e-5f) * lng[c] + lnb[c];
    g_X[((size_t)b * NK + pos) * DD + c] = y;
}

// ---------------- scores v2: tile 128q x 64k, full DK=64 in smem ----------------
// grid (NK/64, NQ/128, NBH). Warp grid 4(q)x2(k), warp tile 32x32, thread 4x8.
__global__ __launch_bounds__(256) void scores2_kernel()
{
    __shared__ float Qs[64][128];   // [d][q]  32KB
    __shared__ float Ks[64][64];    // [d][k]  16KB
    const int bh = blockIdx.z;
    const int b = bh >> 3, h = bh & 7;
    const int q0 = blockIdx.y * 128;
    const int k0 = blockIdx.x * 64;
    const int tid = threadIdx.x;
    const int lane = tid & 31;
    const int warp = tid >> 5;
    const int warpM = warp >> 1;         // 0..3 -> q rows
    const int warpN = warp & 1;          // 0..1 -> k cols
    const int tm = lane >> 2;            // 0..7
    const int tn = lane & 3;             // 0..3
    const int rq = warpM * 32 + tm * 4;
    const int ck = warpN * 32 + tn * 8;

    // load Q tile: 128 rows x 64 dims
    {
        const int qr = tid >> 1;
        const int d0 = (tid & 1) * 4;
        const float* src = g_Q + ((size_t)b * NQ + q0 + qr) * DD + h * DK_;
#pragma unroll
        for (int it = 0; it < 8; it++) {
            int d = d0 + it * 8;
            float4 v = *reinterpret_cast<const float4*>(src + d);
            Qs[d + 0][qr] = v.x; Qs[d + 1][qr] = v.y; Qs[d + 2][qr] = v.z; Qs[d + 3][qr] = v.w;
        }
    }
    // load K tile: 64 keys x 64 dims
    {
        const int kr = tid >> 2;
        const int d0 = (tid & 3) * 4;
        const float* src = g_K + ((size_t)b * NK + k0 + kr) * DD + h * DK_;
#pragma unroll
        for (int it = 0; it < 4; it++) {
            int d = d0 + it * 16;
            float4 v = *reinterpret_cast<const float4*>(src + d);
            Ks[d + 0][kr] = v.x; Ks[d + 1][kr] = v.y; Ks[d + 2][kr] = v.z; Ks[d + 3][kr] = v.w;
        }
    }
    __syncthreads();

    float acc[4][8] = {};
#pragma unroll
    for (int kk = 0; kk < 64; kk++) {
        float4 a = *reinterpret_cast<const float4*>(&Qs[kk][rq]);
        float4 b0 = *reinterpret_cast<const float4*>(&Ks[kk][ck]);
        float4 b1 = *reinterpret_cast<const float4*>(&Ks[kk][ck + 4]);
        float av[4] = { a.x, a.y, a.z, a.w };
        float bv[8] = { b0.x, b0.y, b0.z, b0.w, b1.x, b1.y, b1.z, b1.w };
#pragma unroll
        for (int i = 0; i < 4; i++)
#pragma unroll
            for (int j = 0; j < 8; j++) acc[i][j] = fmaf(av[i], bv[j], acc[i][j]);
    }
    const float scale = 0.125f;
#pragma unroll
    for (int i = 0; i < 4; i++) {
        int qq = q0 + rq + i;
        float* dst = g_att + ((size_t)bh * NQ + qq) * NK + k0 + ck;
        float4 v0 = { acc[i][0] * scale, acc[i][1] * scale, acc[i][2] * scale, acc[i][3] * scale };
        float4 v1 = { acc[i][4] * scale, acc[i][5] * scale, acc[i][6] * scale, acc[i][7] * scale };
        *reinterpret_cast<float4*>(dst) = v0;
        *reinterpret_cast<float4*>(dst + 4) = v1;
    }
}

__global__ void zero_stats_kernel() {
    if (threadIdx.x < NBH) g_ssq[threadIdx.x] = 0.f;
}

// ---------------- head-mix + softmax + centered ssq, warp-per-head ----------------
// grid (B*NQ), 256 thr = 8 warps. Warp o handles output head o. In-place on g_att.
__global__ __launch_bounds__(256) void headmix2_kernel(
    const float* __restrict__ tw, const float* __restrict__ tb)
{
    __shared__ float raw[8][256];
    const int bq = blockIdx.x;
    const int b = bq / NQ, q = bq % NQ;
    const int tid = threadIdx.x;
    const int lane = tid & 31;
    const int o = tid >> 5;                 // warp = output head

    const size_t rowbase = ((size_t)b * NHH * NQ + q) * NK;
#pragma unroll
    for (int i = 0; i < 8; i++) raw[i][tid] = g_att[rowbase + (size_t)i * NQ * NK + tid];
    __syncthreads();

    float w0 = tw[o * 8 + 0], w1 = tw[o * 8 + 1], w2 = tw[o * 8 + 2], w3 = tw[o * 8 + 3];
    float w4 = tw[o * 8 + 4], w5 = tw[o * 8 + 5], w6 = tw[o * 8 + 6], w7 = tw[o * 8 + 7];
    float bias = tb[o];

    float m[8];
    float mx = -3.4e38f;
#pragma unroll
    for (int j = 0; j < 8; j++) {
        int k = lane + 32 * j;
        float v = bias;
        v = fmaf(w0, raw[0][k], v); v = fmaf(w1, raw[1][k], v);
        v = fmaf(w2, raw[2][k], v); v = fmaf(w3, raw[3][k], v);
        v = fmaf(w4, raw[4][k], v); v = fmaf(w5, raw[5][k], v);
        v = fmaf(w6, raw[6][k], v); v = fmaf(w7, raw[7][k], v);
        m[j] = v;
        mx = fmaxf(mx, v);
    }
#pragma unroll
    for (int off = 16; off > 0; off >>= 1) mx = fmaxf(mx, __shfl_xor_sync(0xffffffffu, mx, off));

    float sum = 0.f;
#pragma unroll
    for (int j = 0; j < 8; j++) { m[j] = __expf(m[j] - mx); sum += m[j]; }
#pragma unroll
    for (int off = 16; off > 0; off >>= 1) sum += __shfl_xor_sync(0xffffffffu, sum, off);

    const float inv = 1.f / sum;
    float* dst = g_att + rowbase + (size_t)o * NQ * NK;
    float ssq = 0.f;
#pragma unroll
    for (int j = 0; j < 8; j++) {
        float c = m[j] * inv - 0.00390625f;   // p - 1/256 (analytic IN mean)
        dst[lane + 32 * j] = c;
        ssq = fmaf(c, c, ssq);
    }
#pragma unroll
    for (int off = 16; off > 0; off >>= 1) ssq += __shfl_xor_sync(0xffffffffu, ssq, off);
    if (lane == 0) atomicAdd(&g_ssq[b * 8 + o], ssq);
}

__global__ void rstd_kernel() {
    int i = threadIdx.x;
    if (i < NBH) g_rstd[i] = rsqrtf(g_ssq[i] * (1.f / ((float)NQ * (float)NK)) + 1e-5f);
}

// ---------------- att @ V, InstanceNorm folded. Tile 128q x 64d, k-chunks 32 ----------------
// grid (NQ/128, NBH). Same warp layout as scores. Writes O into g_Q.
__global__ __launch_bounds__(256) void attv2_kernel()
{
    __shared__ float Atts[32][128];   // [k][q] 16KB
    __shared__ float Vs[32][68];      // [k][d] 8.5KB (pad 68 vs store conflicts)
    const int bh = blockIdx.y;
    const int b = bh >> 3, h = bh & 7;
    const int q0 = blockIdx.x * 128;
    const int tid = threadIdx.x;
    const int lane = tid & 31;
    const int warp = tid >> 5;
    const int warpM = warp >> 1;
    const int warpN = warp & 1;
    const int tm = lane >> 2;
    const int tn = lane & 3;
    const int rq = warpM * 32 + tm * 4;
    const int cd = warpN * 32 + tn * 8;

    const int qr = tid >> 1;                      // att loads
    const int kc = (tid & 1) * 4;
    const int vk = tid >> 3;                      // V loads: key row 0..31
    const int vd = (tid & 7) * 4;

    const float* Abase = g_att + ((size_t)bh * NQ + q0 + qr) * NK;
    const float* Vbase = g_V + ((size_t)b * NK) * DD + h * DK_;

    float acc[4][8] = {};
    for (int c0 = 0; c0 < NK; c0 += 32) {
        // load att chunk [32k][128q]
#pragma unroll
        for (int it = 0; it < 4; it++) {
            int k = kc + it * 8;
            float4 v = *reinterpret_cast<const float4*>(Abase + c0 + k);
            Atts[k + 0][qr] = v.x; Atts[k + 1][qr] = v.y; Atts[k + 2][qr] = v.z; Atts[k + 3][qr] = v.w;
        }
        // load V chunk [32k][64d]
        {
            const float* src = Vbase + (size_t)(c0 + vk) * DD;
            float4 v0 = *reinterpret_cast<const float4*>(src + vd);
            float4 v1 = *reinterpret_cast<const float4*>(src + vd + 32);
            *reinterpret_cast<float4*>(&Vs[vk][vd]) = v0;
            *reinterpret_cast<float4*>(&Vs[vk][vd + 32]) = v1;
        }
        __syncthreads();
#pragma unroll
        for (int kk = 0; kk < 32; kk++) {
            float4 a = *reinterpret_cast<const float4*>(&Atts[kk][rq]);
            float4 b0 = *reinterpret_cast<const float4*>(&Vs[kk][cd]);
            float4 b1 = *reinterpret_cast<const float4*>(&Vs[kk][cd + 4]);
            float av[4] = { a.x, a.y, a.z, a.w };
            float bv[8] = { b0.x, b0.y, b0.z, b0.w, b1.x, b1.y, b1.z, b1.w };
#pragma unroll
            for (int i = 0; i < 4; i++)
#pragma unroll
                for (int j = 0; j < 8; j++) acc[i][j] = fmaf(av[i], bv[j], acc[i][j]);
        }
        __syncthreads();
    }
    const float rs = g_rstd[bh];
#pragma unroll
    for (int i = 0; i < 4; i++) {
        int qq = q0 + rq + i;
        float* dst = g_Q + ((size_t)b * NQ + qq) * DD + h * DK_ + cd;
        float4 v0 = { acc[i][0] * rs, acc[i][1] * rs, acc[i][2] * rs, acc[i][3] * rs };
        float4 v1 = { acc[i][4] * rs, acc[i][5] * rs, acc[i][6] * rs, acc[i][7] * rs };
        *reinterpret_cast<float4*>(dst) = v0;
        *reinterpret_cast<float4*>(dst + 4) = v1;
    }
}

// ---------------- launch ----------------
extern "C" void kernel_launch(void* const* d_in, const int* in_sizes, int n_in,
                              void* d_out, int out_size)
{
    const float* queries = (const float*)d_in[0];
    const float* Wq = (const float*)d_in[1];
    const float* bq = (const float*)d_in[2];
    const float* Wk = (const float*)d_in[3];
    const float* bk = (const float*)d_in[4];
    const float* Wv = (const float*)d_in[5];
    const float* bv = (const float*)d_in[6];
    const float* Wo = (const float*)d_in[7];
    const float* bo = (const float*)d_in[8];
    const float* srw = (const float*)d_in[9];
    const float* srb = (const float*)d_in[10];
    const float* lng = (const float*)d_in[11];
    const float* lnb = (const float*)d_in[12];
    const float* tw = (const float*)d_in[13];
    const float* tb = (const float*)d_in[14];
    float* out = (float*)d_out;

    float *pQ, *pX, *pK, *pV;
    cudaGetSymbolAddress((void**)&pQ, g_Q);
    cudaGetSymbolAddress((void**)&pX, g_X);
    cudaGetSymbolAddress((void**)&pK, g_K);
    cudaGetSymbolAddress((void**)&pV, g_V);

    // 1. Q projection
    sgemm2_kernel<<<dim3(DD / 128, (BB * NQ) / 128), 256>>>(queries, Wq, bq, pQ, BB * NQ, DD, DD);

    // 2. conv + LayerNorm
    conv_ln_kernel<<<dim3(NK, BB), 512>>>(queries, srw, srb, lng, lnb);

    // 3/4. K, V projections
    sgemm2_kernel<<<dim3(DD / 128, (BB * NK) / 128), 256>>>(pX, Wk, bk, pK, BB * NK, DD, DD);
    sgemm2_kernel<<<dim3(DD / 128, (BB * NK) / 128), 256>>>(pX, Wv, bv, pV, BB * NK, DD, DD);

    // 5. attention scores
    scores2_kernel<<<dim3(NK / 64, NQ / 128, NBH), 256>>>();

    // 6. zero InstanceNorm accumulators
    zero_stats_kernel<<<1, 128>>>();

    // 7. head mix + softmax + centered ssq (in-place)
    headmix2_kernel<<<BB * NQ, 256>>>(tw, tb);

    // 8. finalize rstd
    rstd_kernel<<<1, 128>>>();

    // 9. normalized att @ V -> g_Q
    attv2_kernel<<<dim3(NQ / 128, NBH), 256>>>();

    // 10. output projection
    sgemm2_kernel<<<dim3(DD / 128, (BB * NQ) / 128), 256>>>(pQ, Wo, bo, out, BB * NQ, DD, DD);
}